// round 1
// baseline (speedup 1.0000x reference)
#include <cuda_runtime.h>
#include <cub/cub.cuh>
#include <math.h>

#define N_ANCH   172032
#define MAX_OUT  200
#define NMS_TH   0.4f
#define BLK      1024

// ---- static device scratch (no dynamic allocation allowed) ----
__device__ float g_keys_in[N_ANCH];
__device__ int   g_vals_in[N_ANCH];
__device__ float g_keys_out[N_ANCH];
__device__ int   g_vals_out[N_ANCH];
__device__ unsigned char g_cub_temp[16 * 1024 * 1024];
__device__ int   g_sel_idx[MAX_OUT];
__device__ int   g_sel_valid[MAX_OUT];

// ---------------- prep: extract score keys + index values ----------------
__global__ void prep_kernel(const float* __restrict__ cls, int n) {
    int i = blockIdx.x * blockDim.x + threadIdx.x;
    if (i < n) {
        g_keys_in[i] = cls[2 * i + 1];
        g_vals_in[i] = i;
    }
}

// ---------------- decode helper (matches reference _decode) ----------------
__device__ __forceinline__ void decode_box(const float4& rg, const float4& an,
                                           float& y1, float& x1, float& y2, float& x2,
                                           float& ar) {
    float dx = rg.x * 0.1f, dy = rg.y * 0.1f, dw = rg.z * 0.2f, dh = rg.w * 0.2f;
    float xc = dx * an.z + an.x;
    float yc = dy * an.w + an.y;
    float w  = expf(dw) * an.z;
    float h  = expf(dh) * an.w;
    y1 = yc - 0.5f * h;  x1 = xc - 0.5f * w;
    y2 = yc + 0.5f * h;  x2 = xc + 0.5f * w;
    ar = (y2 - y1) * (x2 - x1);
}

// ---------------- greedy NMS over sorted candidates (single block) ----------------
__global__ __launch_bounds__(BLK) void nms_kernel(const float* __restrict__ reg,
                                                  const float* __restrict__ anch,
                                                  int n) {
    __shared__ float s_y1[BLK], s_x1[BLK], s_y2[BLK], s_x2[BLK], s_ar[BLK];
    __shared__ int   s_idx[BLK];
    __shared__ unsigned char s_alive[BLK];
    __shared__ float q_y1[MAX_OUT], q_x1[MAX_OUT], q_y2[MAX_OUT], q_x2[MAX_OUT], q_ar[MAX_OUT];

    const int t = threadIdx.x;
    int nsel = 0;   // uniform across block

    for (int base = 0; base < n; base += BLK) {
        int r = base + t;
        float sc = -1e30f;
        int idx = 0;
        if (r < n) { sc = g_keys_out[r]; idx = g_vals_out[r]; }
        bool ok = (sc > NMS_TH);

        float y1 = 0.f, x1 = 0.f, y2 = 0.f, x2 = 0.f, ar = 0.f;
        if (ok) {
            float4 rg = __ldg(reinterpret_cast<const float4*>(reg) + idx);
            float4 an = __ldg(reinterpret_cast<const float4*>(anch) + idx);
            decode_box(rg, an, y1, x1, y2, x2, ar);
        }

        // filter against already-selected queue (from previous chunks)
        bool alive = ok;
        for (int s = 0; s < nsel && alive; s++) {
            float ih = fmaxf(fminf(y2, q_y2[s]) - fmaxf(y1, q_y1[s]), 0.f);
            float iw = fmaxf(fminf(x2, q_x2[s]) - fmaxf(x1, q_x1[s]), 0.f);
            float inter = ih * iw;
            float iou = inter / (ar + q_ar[s] - inter + 1e-12f);
            if (iou > NMS_TH) alive = false;
        }

        s_y1[t] = y1; s_x1[t] = x1; s_y2[t] = y2; s_x2[t] = x2; s_ar[t] = ar;
        s_idx[t] = idx;
        s_alive[t] = alive ? 1 : 0;
        __syncthreads();

        // serial resolve within chunk (uniform control flow)
        for (int i = 0; i < BLK; i++) {
            if (nsel >= MAX_OUT) break;
            if (!s_alive[i]) continue;
            float by1 = s_y1[i], bx1 = s_x1[i], by2 = s_y2[i], bx2 = s_x2[i], bar = s_ar[i];
            if (t == 0) {
                g_sel_idx[nsel] = s_idx[i];
                q_y1[nsel] = by1; q_x1[nsel] = bx1;
                q_y2[nsel] = by2; q_x2[nsel] = bx2; q_ar[nsel] = bar;
            }
            if (t > i && alive) {
                float ih = fmaxf(fminf(y2, by2) - fmaxf(y1, by1), 0.f);
                float iw = fmaxf(fminf(x2, bx2) - fmaxf(x1, bx1), 0.f);
                float inter = ih * iw;
                float iou = inter / (ar + bar - inter + 1e-12f);
                if (iou > NMS_TH) { alive = false; s_alive[t] = 0; }
            }
            nsel++;
            __syncthreads();
        }
        __syncthreads();

        if (nsel >= MAX_OUT) break;
        // sorted descending: if the last score in this chunk is already <= thresh,
        // no further chunk can contain a valid candidate
        int last = min(base + BLK - 1, n - 1);
        if (g_keys_out[last] <= NMS_TH) break;
    }

    for (int j = t; j < MAX_OUT; j += BLK) {
        if (j < nsel) {
            g_sel_valid[j] = 1;
        } else {
            g_sel_valid[j] = 0;
            g_sel_idx[j] = 0;
        }
    }
}

// ---------------- gather: decode boxes + landmarks for selected, write output ----------------
__global__ void gather_kernel(const float* __restrict__ reg,
                              const float* __restrict__ lnd,
                              const float* __restrict__ anch,
                              float* __restrict__ out) {
    int t = blockIdx.x * blockDim.x + threadIdx.x;
    if (t >= MAX_OUT) return;
    int idx = g_sel_idx[t];
    float m = g_sel_valid[t] ? 1.f : 0.f;

    float4 rg = __ldg(reinterpret_cast<const float4*>(reg) + idx);
    float4 an = __ldg(reinterpret_cast<const float4*>(anch) + idx);
    float y1, x1, y2, x2, ar;
    decode_box(rg, an, y1, x1, y2, x2, ar);

    out[4 * t + 0] = y1 * m;
    out[4 * t + 1] = x1 * m;
    out[4 * t + 2] = y2 * m;
    out[4 * t + 3] = x2 * m;

    const float* lp = lnd + 10 * idx;
    float* op = out + 4 * MAX_OUT + 10 * t;
#pragma unroll
    for (int k = 0; k < 5; k++) {
        float lx = lp[2 * k]     * 0.1f * an.z + an.x;
        float ly = lp[2 * k + 1] * 0.1f * an.w + an.y;
        op[2 * k]     = lx * m;
        op[2 * k + 1] = ly * m;
    }
}

// ---------------- launch ----------------
extern "C" void kernel_launch(void* const* d_in, const int* in_sizes, int n_in,
                              void* d_out, int out_size) {
    const float* cls  = (const float*)d_in[0];
    const float* reg  = (const float*)d_in[1];
    const float* lnd  = (const float*)d_in[2];
    const float* anch = (const float*)d_in[3];

    int n = in_sizes[0] / 2;
    if (n > N_ANCH) n = N_ANCH;

    float *ki = nullptr, *ko = nullptr;
    int *vi = nullptr, *vo = nullptr;
    void* tmp = nullptr;
    cudaGetSymbolAddress((void**)&ki, g_keys_in);
    cudaGetSymbolAddress((void**)&ko, g_keys_out);
    cudaGetSymbolAddress((void**)&vi, g_vals_in);
    cudaGetSymbolAddress((void**)&vo, g_vals_out);
    cudaGetSymbolAddress(&tmp, g_cub_temp);

    prep_kernel<<<(n + 255) / 256, 256>>>(cls, n);

    size_t temp_bytes = 0;
    cub::DeviceRadixSort::SortPairsDescending(nullptr, temp_bytes,
                                              ki, ko, vi, vo, n,
                                              0, 32, (cudaStream_t)0);
    if (temp_bytes <= sizeof(g_cub_temp)) {
        cub::DeviceRadixSort::SortPairsDescending(tmp, temp_bytes,
                                                  ki, ko, vi, vo, n,
                                                  0, 32, (cudaStream_t)0);
    }

    nms_kernel<<<1, BLK>>>(reg, anch, n);
    gather_kernel<<<1, 256>>>(reg, lnd, anch, (float*)d_out);
}